// round 14
// baseline (speedup 1.0000x reference)
#include <cuda_runtime.h>

// B=32, P=3, D=300, N=2048.  x,y: [B,P,D,N] fp32.
// out: [B, P*N, 3] = {cos, l2, l1} per (b,p,n) vector of length D (stride N).
//
// CH=8: largest pipeline depth fitting the 255-reg ceiling (CH=10 hit 254
// and collapsed, R13). 37 ping-pong chunks cover rows 0..295; the 4-row tail
// is loaded into its own buffer right after the prolog so its latency is
// hidden under the whole mainloop. Steady state: 32 LDG.128/thread
// (~166KB/SM in flight; R12's 24/125KB gave 85.5% DRAM).

#define D_DIM 300
#define CH 8                  // d-rows per chunk
#define NCHUNK 37             // 37*8 = 296 rows
#define TAIL 4                // rows 296..299
#define N_DIM 2048
#define N4 (N_DIM / 4)        // 512
#define BP 96
#define THREADS 32

__device__ __forceinline__ float4 ldg4_nc(const float4* p)
{
    float4 v;
    asm("ld.global.nc.L2::256B.v4.f32 {%0, %1, %2, %3}, [%4];"
        : "=f"(v.x), "=f"(v.y), "=f"(v.z), "=f"(v.w) : "l"(p));
    return v;
}

#define LOAD_CHUNK(A_, B_, base)                                    \
    do {                                                            \
        const size_t _o = (size_t)(base) * N4;                      \
        _Pragma("unroll")                                           \
        for (int _i = 0; _i < CH; ++_i) {                           \
            A_[_i] = ldg4_nc(xp + _o + (size_t)_i * N4);            \
            B_[_i] = ldg4_nc(yp + _o + (size_t)_i * N4);            \
        }                                                           \
    } while (0)

#define COMPUTE4(_av, _bv)                                          \
    do {                                                            \
        const float _ax[4] = {(_av).x, (_av).y, (_av).z, (_av).w};  \
        const float _bx[4] = {(_bv).x, (_bv).y, (_bv).z, (_bv).w};  \
        _Pragma("unroll")                                           \
        for (int _j = 0; _j < 4; ++_j) {                            \
            const float _a = _ax[_j], _b = _bx[_j];                 \
            dot[_j] = fmaf(_a, _b, dot[_j]);                        \
            xx [_j] = fmaf(_a, _a, xx [_j]);                        \
            yy [_j] = fmaf(_b, _b, yy [_j]);                        \
            const float _d = _a - _b;                               \
            dd [_j] = fmaf(_d, _d, dd [_j]);                        \
            l1 [_j] += fabsf(_d);                                   \
        }                                                           \
    } while (0)

#define COMPUTE_CHUNK(A_, B_)                                       \
    do {                                                            \
        _Pragma("unroll")                                           \
        for (int _i = 0; _i < CH; ++_i)                             \
            COMPUTE4(A_[_i], B_[_i]);                               \
    } while (0)

__global__ __launch_bounds__(THREADS)
void sim_measure_kernel(const float* __restrict__ x,
                        const float* __restrict__ y,
                        float* __restrict__ out)
{
    const int idx = blockIdx.x * THREADS + threadIdx.x;   // float4-column id
    const int n4 = idx & (N4 - 1);
    const int bp = idx >> 9;                              // / 512

    const float4* __restrict__ xp =
        reinterpret_cast<const float4*>(x) + (size_t)bp * D_DIM * N4 + n4;
    const float4* __restrict__ yp =
        reinterpret_cast<const float4*>(y) + (size_t)bp * D_DIM * N4 + n4;

    float dot[4] = {0.f, 0.f, 0.f, 0.f};
    float xx [4] = {0.f, 0.f, 0.f, 0.f};
    float yy [4] = {0.f, 0.f, 0.f, 0.f};
    float dd [4] = {0.f, 0.f, 0.f, 0.f};
    float l1 [4] = {0.f, 0.f, 0.f, 0.f};

    float4 a0[CH], b0[CH], a1[CH], b1[CH];
    float4 at[TAIL], bt[TAIL];

    LOAD_CHUNK(a0, b0, 0 * CH);
    LOAD_CHUNK(a1, b1, 1 * CH);

    // tail rows 296..299 loaded up front; latency hidden under the mainloop
    {
        const size_t _o = (size_t)(NCHUNK * CH) * N4;
        #pragma unroll
        for (int i = 0; i < TAIL; ++i) {
            at[i] = ldg4_nc(xp + _o + (size_t)i * N4);
            bt[i] = ldg4_nc(yp + _o + (size_t)i * N4);
        }
    }

    // NCHUNK = 37 (odd): loop (c = 0,2,..,32) computes chunks 0..33 and
    // loads 2..35; epilogue computes 34, loads 36, computes 35, computes 36.
    #pragma unroll 1
    for (int c = 0; c + 3 < NCHUNK; c += 2) {
        COMPUTE_CHUNK(a0, b0);
        LOAD_CHUNK(a0, b0, (c + 2) * CH);
        COMPUTE_CHUNK(a1, b1);
        LOAD_CHUNK(a1, b1, (c + 3) * CH);
    }
    COMPUTE_CHUNK(a0, b0);                    // chunk 34
    LOAD_CHUNK(a0, b0, (NCHUNK - 1) * CH);    // chunk 36
    COMPUTE_CHUNK(a1, b1);                    // chunk 35
    COMPUTE_CHUNK(a0, b0);                    // chunk 36

    #pragma unroll
    for (int i = 0; i < TAIL; ++i)
        COMPUTE4(at[i], bt[i]);

    // out layout: [bp, n, 3], 4 consecutive n per thread
    const int n0 = n4 * 4;
    float* o = out + ((size_t)bp * N_DIM + n0) * 3;
    #pragma unroll
    for (int j = 0; j < 4; ++j) {
        o[j * 3 + 0] = dot[j] * rsqrtf(xx[j] * yy[j]);
        o[j * 3 + 1] = sqrtf(dd[j]);
        o[j * 3 + 2] = l1[j];
    }
}

extern "C" void kernel_launch(void* const* d_in, const int* in_sizes, int n_in,
                              void* d_out, int out_size)
{
    const float* x = (const float*)d_in[0];
    const float* y = (const float*)d_in[1];
    float* out = (float*)d_out;

    const int total_threads = BP * N4;           // 49152
    const int blocks = total_threads / THREADS;  // 1536
    sim_measure_kernel<<<blocks, THREADS>>>(x, y, out);
}

// round 15
// speedup vs baseline: 1.0102x; 1.0102x over previous
#include <cuda_runtime.h>
#include <cstdint>

// B=32, P=3, D=300, N=2048.  x,y: [B,P,D,N] fp32.
// out: [B, P*N, 3] = {cos, l2, l1} per (b,p,n) vector of length D (stride N).
//
// cp.async pipeline: in-flight data lives in SMEM, not registers (register
// ping-pong capped at CH=6/regs=128/85.5% DRAM; CH>=8 hit the 255-reg cliff
// twice). 5-stage ring x 4 rows x 2 operands = 20KB smem/block; steady state
// 4 stages (32 LDGSTS x 16B = 16KB/warp, ~166KB/SM in flight) at regs ~50.
// Each thread copies and consumes ONLY its own 16B/row -> no __syncthreads,
// just per-thread cp.async.wait_group. Same 1536x32 float4-column mapping.

#define D_DIM 300
#define R 4                   // d-rows per stage
#define STAGES 5
#define NSTAGE (D_DIM / R)    // 75
#define N_DIM 2048
#define N4 (N_DIM / 4)        // 512
#define BP 96
#define THREADS 32

#define ISSUE_STAGE(slot_, stage_)                                          \
    do {                                                                    \
        const size_t _rb = (size_t)(stage_) * R;                            \
        _Pragma("unroll")                                                   \
        for (int _r = 0; _r < R; ++_r) {                                    \
            uint32_t _sx = (uint32_t)__cvta_generic_to_shared(              \
                &sbuf[slot_][0][_r][lane]);                                 \
            uint32_t _sy = (uint32_t)__cvta_generic_to_shared(              \
                &sbuf[slot_][1][_r][lane]);                                 \
            asm volatile(                                                   \
                "cp.async.cg.shared.global.L2::256B [%0], [%1], 16;"        \
                :: "r"(_sx), "l"(xp + (_rb + _r) * N4) : "memory");         \
            asm volatile(                                                   \
                "cp.async.cg.shared.global.L2::256B [%0], [%1], 16;"        \
                :: "r"(_sy), "l"(yp + (_rb + _r) * N4) : "memory");         \
        }                                                                   \
        asm volatile("cp.async.commit_group;" ::: "memory");                \
    } while (0)

#define COMMIT_EMPTY() \
    asm volatile("cp.async.commit_group;" ::: "memory")

#define WAIT_GROUPS(n_) \
    asm volatile("cp.async.wait_group %0;" :: "n"(n_) : "memory")

#define CONSUME_STAGE(slot_)                                                \
    do {                                                                    \
        _Pragma("unroll")                                                   \
        for (int _r = 0; _r < R; ++_r) {                                    \
            const float4 _a = sbuf[slot_][0][_r][lane];                     \
            const float4 _b = sbuf[slot_][1][_r][lane];                     \
            const float _ax[4] = {_a.x, _a.y, _a.z, _a.w};                  \
            const float _bx[4] = {_b.x, _b.y, _b.z, _b.w};                  \
            _Pragma("unroll")                                               \
            for (int _j = 0; _j < 4; ++_j) {                                \
                const float _av = _ax[_j], _bv = _bx[_j];                   \
                dot[_j] = fmaf(_av, _bv, dot[_j]);                          \
                xx [_j] = fmaf(_av, _av, xx [_j]);                          \
                yy [_j] = fmaf(_bv, _bv, yy [_j]);                          \
                const float _d = _av - _bv;                                 \
                dd [_j] = fmaf(_d, _d, dd [_j]);                            \
                l1 [_j] += fabsf(_d);                                       \
            }                                                               \
        }                                                                   \
    } while (0)

__global__ __launch_bounds__(THREADS)
void sim_measure_kernel(const float* __restrict__ x,
                        const float* __restrict__ y,
                        float* __restrict__ out)
{
    __shared__ alignas(16) float4 sbuf[STAGES][2][R][THREADS];  // 20 KB

    const int lane = threadIdx.x;
    const int idx = blockIdx.x * THREADS + lane;
    const int n4 = idx & (N4 - 1);
    const int bp = idx >> 9;                              // / 512

    const float4* __restrict__ xp =
        reinterpret_cast<const float4*>(x) + (size_t)bp * D_DIM * N4 + n4;
    const float4* __restrict__ yp =
        reinterpret_cast<const float4*>(y) + (size_t)bp * D_DIM * N4 + n4;

    float dot[4] = {0.f, 0.f, 0.f, 0.f};
    float xx [4] = {0.f, 0.f, 0.f, 0.f};
    float yy [4] = {0.f, 0.f, 0.f, 0.f};
    float dd [4] = {0.f, 0.f, 0.f, 0.f};
    float l1 [4] = {0.f, 0.f, 0.f, 0.f};

    // prolog: stages 0..3 in flight (4 committed groups)
    ISSUE_STAGE(0, 0);
    ISSUE_STAGE(1, 1);
    ISSUE_STAGE(2, 2);
    ISSUE_STAGE(3, 3);

    // iter t: wait until stage t landed (<=3 newer groups outstanding),
    // top up with stage t+4 (slot (t+4)%5, last used by stage t-1, already
    // consumed), then consume stage t. Unroll 5 -> slot indices are
    // compile-time, smem addressing static.
    #pragma unroll 5
    for (int t = 0; t < NSTAGE; ++t) {
        WAIT_GROUPS(3);
        const int s = t + STAGES - 1;
        if (s < NSTAGE) {
            ISSUE_STAGE(s % STAGES, s);
        } else {
            COMMIT_EMPTY();
        }
        CONSUME_STAGE(t % STAGES);
    }

    // out layout: [bp, n, 3], 4 consecutive n per thread
    const int n0 = n4 * 4;
    float* o = out + ((size_t)bp * N_DIM + n0) * 3;
    #pragma unroll
    for (int j = 0; j < 4; ++j) {
        o[j * 3 + 0] = dot[j] * rsqrtf(xx[j] * yy[j]);
        o[j * 3 + 1] = sqrtf(dd[j]);
        o[j * 3 + 2] = l1[j];
    }
}

extern "C" void kernel_launch(void* const* d_in, const int* in_sizes, int n_in,
                              void* d_out, int out_size)
{
    const float* x = (const float*)d_in[0];
    const float* y = (const float*)d_in[1];
    float* out = (float*)d_out;

    const int total_threads = BP * N4;           // 49152
    const int blocks = total_threads / THREADS;  // 1536
    sim_measure_kernel<<<blocks, THREADS>>>(x, y, out);
}

// round 16
// speedup vs baseline: 1.0193x; 1.0090x over previous
#include <cuda_runtime.h>

// B=32, P=3, D=300, N=2048.  x,y: [B,P,D,N] fp32.
// out: [B, P*N, 3] = {cos, l2, l1} per (b,p,n) vector of length D (stride N).
//
// R12 champion (float4/thread, 1536x32, CH=6 register ping-pong, regs 128,
// 85.5% DRAM) + prefetch.global.L2 for chunks c+4/c+5: extends the memory
// look-ahead ~2x without spending registers (CH>=8 hit the 255-reg cliff) or
// smem (cp.async staging was overhead-negative, R15). One lane per 128B line
// issues the prefetch -> 2 predicated issue slots per row, issue has slack.

#define D_DIM 300
#define CH 6                  // d-rows per chunk
#define NCHUNK (D_DIM / CH)   // 50
#define N_DIM 2048
#define N4 (N_DIM / 4)        // 512
#define BP 96
#define THREADS 32

__device__ __forceinline__ float4 ldg4_nc(const float4* p)
{
    float4 v;
    asm("ld.global.nc.L2::256B.v4.f32 {%0, %1, %2, %3}, [%4];"
        : "=f"(v.x), "=f"(v.y), "=f"(v.z), "=f"(v.w) : "l"(p));
    return v;
}

#define LOAD_CHUNK(A_, B_, base)                                    \
    do {                                                            \
        const size_t _o = (size_t)(base) * N4;                      \
        _Pragma("unroll")                                           \
        for (int _i = 0; _i < CH; ++_i) {                           \
            A_[_i] = ldg4_nc(xp + _o + (size_t)_i * N4);            \
            B_[_i] = ldg4_nc(yp + _o + (size_t)_i * N4);            \
        }                                                           \
    } while (0)

// Prefetch one future chunk into L2. Lanes 0,8,16,24 each cover one 128B
// line of the warp's 512B row-slab (for both operands).
#define PREFETCH_CHUNK(chunk_)                                      \
    do {                                                            \
        if ((chunk_) < NCHUNK && (lane & 7) == 0) {                 \
            const size_t _o = (size_t)(chunk_) * CH * N4;           \
            _Pragma("unroll")                                       \
            for (int _i = 0; _i < CH; ++_i) {                       \
                asm volatile("prefetch.global.L2 [%0];"             \
                             :: "l"(xp + _o + (size_t)_i * N4));    \
                asm volatile("prefetch.global.L2 [%0];"             \
                             :: "l"(yp + _o + (size_t)_i * N4));    \
            }                                                       \
        }                                                           \
    } while (0)

#define COMPUTE_CHUNK(A_, B_)                                       \
    do {                                                            \
        _Pragma("unroll")                                           \
        for (int _i = 0; _i < CH; ++_i) {                           \
            const float _ax[4] = {A_[_i].x, A_[_i].y, A_[_i].z, A_[_i].w}; \
            const float _bx[4] = {B_[_i].x, B_[_i].y, B_[_i].z, B_[_i].w}; \
            _Pragma("unroll")                                       \
            for (int _j = 0; _j < 4; ++_j) {                        \
                const float _a = _ax[_j], _b = _bx[_j];             \
                dot[_j] = fmaf(_a, _b, dot[_j]);                    \
                xx [_j] = fmaf(_a, _a, xx [_j]);                    \
                yy [_j] = fmaf(_b, _b, yy [_j]);                    \
                const float _d = _a - _b;                           \
                dd [_j] = fmaf(_d, _d, dd [_j]);                    \
                l1 [_j] += fabsf(_d);                               \
            }                                                       \
        }                                                           \
    } while (0)

__global__ __launch_bounds__(THREADS)
void sim_measure_kernel(const float* __restrict__ x,
                        const float* __restrict__ y,
                        float* __restrict__ out)
{
    const int lane = threadIdx.x;
    const int idx = blockIdx.x * THREADS + lane;          // float4-column id
    const int n4 = idx & (N4 - 1);
    const int bp = idx >> 9;                              // / 512

    const float4* __restrict__ xp =
        reinterpret_cast<const float4*>(x) + (size_t)bp * D_DIM * N4 + n4;
    const float4* __restrict__ yp =
        reinterpret_cast<const float4*>(y) + (size_t)bp * D_DIM * N4 + n4;

    float dot[4] = {0.f, 0.f, 0.f, 0.f};
    float xx [4] = {0.f, 0.f, 0.f, 0.f};
    float yy [4] = {0.f, 0.f, 0.f, 0.f};
    float dd [4] = {0.f, 0.f, 0.f, 0.f};
    float l1 [4] = {0.f, 0.f, 0.f, 0.f};

    float4 a0[CH], b0[CH], a1[CH], b1[CH];

    LOAD_CHUNK(a0, b0, 0 * CH);
    LOAD_CHUNK(a1, b1, 1 * CH);
    PREFETCH_CHUNK(2);
    PREFETCH_CHUNK(3);

    // NCHUNK = 50 (even): loop (c = 0,2,..,46) computes chunks 0..47 and
    // loads 2..49 (prefetching 4..51, guarded); epilogue computes 48, 49.
    #pragma unroll 1
    for (int c = 0; c + 3 < NCHUNK; c += 2) {
        COMPUTE_CHUNK(a0, b0);
        LOAD_CHUNK(a0, b0, (c + 2) * CH);
        PREFETCH_CHUNK(c + 4);
        COMPUTE_CHUNK(a1, b1);
        LOAD_CHUNK(a1, b1, (c + 3) * CH);
        PREFETCH_CHUNK(c + 5);
    }
    COMPUTE_CHUNK(a0, b0);   // chunk 48
    COMPUTE_CHUNK(a1, b1);   // chunk 49

    // out layout: [bp, n, 3], 4 consecutive n per thread
    const int n0 = n4 * 4;
    float* o = out + ((size_t)bp * N_DIM + n0) * 3;
    #pragma unroll
    for (int j = 0; j < 4; ++j) {
        o[j * 3 + 0] = dot[j] * rsqrtf(xx[j] * yy[j]);
        o[j * 3 + 1] = sqrtf(dd[j]);
        o[j * 3 + 2] = l1[j];
    }
}

extern "C" void kernel_launch(void* const* d_in, const int* in_sizes, int n_in,
                              void* d_out, int out_size)
{
    const float* x = (const float*)d_in[0];
    const float* y = (const float*)d_in[1];
    float* out = (float*)d_out;

    const int total_threads = BP * N4;           // 49152
    const int blocks = total_threads / THREADS;  // 1536
    sim_measure_kernel<<<blocks, THREADS>>>(x, y, out);
}

// round 17
// speedup vs baseline: 1.0486x; 1.0287x over previous
#include <cuda_runtime.h>

// B=32, P=3, D=300, N=2048.  x,y: [B,P,D,N] fp32.
// out: [B, P*N, 3] = {cos, l2, l1} per (b,p,n) vector of length D (stride N).
//
// Tail-balance variant of the R12 champion: float2 per thread, CH=12
// ping-pong, 3072x32 grid -> 20/21 blocks per SM (1.2% imbalance) instead of
// 10/11 (6%). In-flight depth preserved exactly (24 LDG.64/thread, 6KB/warp,
// ~124KB/SM = R12 level, 96 data regs / ~128 total = known-safe budget).
// Warp requests are 256B contiguous = one L2::256B chunk each.

#define D_DIM 300
#define CH 12                 // d-rows per chunk
#define NCHUNK (D_DIM / CH)   // 25
#define N_DIM 2048
#define N2 (N_DIM / 2)        // 1024
#define BP 96
#define THREADS 32

__device__ __forceinline__ float2 ldg2_nc(const float2* p)
{
    float2 v;
    asm("ld.global.nc.L2::256B.v2.f32 {%0, %1}, [%2];"
        : "=f"(v.x), "=f"(v.y) : "l"(p));
    return v;
}

#define LOAD_CHUNK(A_, B_, base)                                    \
    do {                                                            \
        const size_t _o = (size_t)(base) * N2;                      \
        _Pragma("unroll")                                           \
        for (int _i = 0; _i < CH; ++_i) {                           \
            A_[_i] = ldg2_nc(xp + _o + (size_t)_i * N2);            \
            B_[_i] = ldg2_nc(yp + _o + (size_t)_i * N2);            \
        }                                                           \
    } while (0)

#define COMPUTE_CHUNK(A_, B_)                                       \
    do {                                                            \
        _Pragma("unroll")                                           \
        for (int _i = 0; _i < CH; ++_i) {                           \
            const float _a0 = A_[_i].x, _b0 = B_[_i].x;             \
            dot0 = fmaf(_a0, _b0, dot0);                            \
            xx0  = fmaf(_a0, _a0, xx0);                             \
            yy0  = fmaf(_b0, _b0, yy0);                             \
            const float _d0 = _a0 - _b0;                            \
            dd0  = fmaf(_d0, _d0, dd0);                             \
            l10 += fabsf(_d0);                                      \
            const float _a1 = A_[_i].y, _b1 = B_[_i].y;             \
            dot1 = fmaf(_a1, _b1, dot1);                            \
            xx1  = fmaf(_a1, _a1, xx1);                             \
            yy1  = fmaf(_b1, _b1, yy1);                             \
            const float _d1 = _a1 - _b1;                            \
            dd1  = fmaf(_d1, _d1, dd1);                             \
            l11 += fabsf(_d1);                                      \
        }                                                           \
    } while (0)

__global__ __launch_bounds__(THREADS)
void sim_measure_kernel(const float* __restrict__ x,
                        const float* __restrict__ y,
                        float* __restrict__ out)
{
    const int idx = blockIdx.x * THREADS + threadIdx.x;   // float2-column id
    const int n2 = idx & (N2 - 1);
    const int bp = idx >> 10;                             // / 1024

    const float2* __restrict__ xp =
        reinterpret_cast<const float2*>(x) + (size_t)bp * D_DIM * N2 + n2;
    const float2* __restrict__ yp =
        reinterpret_cast<const float2*>(y) + (size_t)bp * D_DIM * N2 + n2;

    float dot0 = 0.f, xx0 = 0.f, yy0 = 0.f, dd0 = 0.f, l10 = 0.f;
    float dot1 = 0.f, xx1 = 0.f, yy1 = 0.f, dd1 = 0.f, l11 = 0.f;

    float2 a0[CH], b0[CH], a1[CH], b1[CH];

    LOAD_CHUNK(a0, b0, 0 * CH);
    LOAD_CHUNK(a1, b1, 1 * CH);

    // NCHUNK = 25 (odd): loop (c = 0,2,..,20) computes chunks 0..21 and
    // loads 2..23; epilogue computes 22, loads 24, computes 23, computes 24.
    #pragma unroll 1
    for (int c = 0; c + 3 < NCHUNK; c += 2) {
        COMPUTE_CHUNK(a0, b0);
        LOAD_CHUNK(a0, b0, (c + 2) * CH);
        COMPUTE_CHUNK(a1, b1);
        LOAD_CHUNK(a1, b1, (c + 3) * CH);
    }
    COMPUTE_CHUNK(a0, b0);                    // chunk 22
    LOAD_CHUNK(a0, b0, (NCHUNK - 1) * CH);    // chunk 24
    COMPUTE_CHUNK(a1, b1);                    // chunk 23
    COMPUTE_CHUNK(a0, b0);                    // chunk 24

    // out layout: [bp, n, 3], n = n2*2 and n2*2+1
    float* o = out + ((size_t)bp * N_DIM + n2 * 2) * 3;
    o[0] = dot0 * rsqrtf(xx0 * yy0);
    o[1] = sqrtf(dd0);
    o[2] = l10;
    o[3] = dot1 * rsqrtf(xx1 * yy1);
    o[4] = sqrtf(dd1);
    o[5] = l11;
}

extern "C" void kernel_launch(void* const* d_in, const int* in_sizes, int n_in,
                              void* d_out, int out_size)
{
    const float* x = (const float*)d_in[0];
    const float* y = (const float*)d_in[1];
    float* out = (float*)d_out;

    const int total_threads = BP * N2;           // 98304
    const int blocks = total_threads / THREADS;  // 3072
    sim_measure_kernel<<<blocks, THREADS>>>(x, y, out);
}